// round 12
// baseline (speedup 1.0000x reference)
#include <cuda_runtime.h>

#define NN 50000
#define KK 15
#define DD 128
#define HH 64
#define NKE (NN*KK)

typedef unsigned long long u64;

// Packed f32x2 helpers (sm_103a FFMA2 path — PTX only, ptxas never emits it).
__device__ __forceinline__ u64 pk2(float lo, float hi) {
    u64 r; asm("mov.b64 %0, {%1, %2};" : "=l"(r) : "f"(lo), "f"(hi)); return r;
}
__device__ __forceinline__ void upk2(u64 v, float& lo, float& hi) {
    asm("mov.b64 {%0, %1}, %2;" : "=f"(lo), "=f"(hi) : "l"(v));
}
__device__ __forceinline__ void fma2(u64& d, u64 a, u64 b) {
    asm("fma.rn.f32x2 %0, %1, %2, %0;" : "+l"(d) : "l"(a), "l"(b));
}

// Precomputed per-node projections (device globals — no allocation allowed).
__device__ float g_hdst[NN*64];   // x @ ew1[0:128]   + eb1
__device__ float g_hsrc[NN*64];   // x @ ew1[128:256]
__device__ float g_gdeg[NN*64];   // x @ dw1[0:128]   + db1

// ---------------------------------------------------------------------------
// Kernel A: three fused 50k x 128 @ 128x64 projections, packed f32x2.
// 512 threads (16 warps, 1 block/SM); warp = 4 nodes; x rows in registers,
// broadcast as 64-bit shfl; weights prepacked {W[2k'],W[2k'+1]} per column.
// Per k-pair: 6 LDS.64 + 8 SHFL + 24 FFMA2 (= 48 lane-FMA).
// ---------------------------------------------------------------------------
__global__ __launch_bounds__(512)
void precompute_kernel(const float* __restrict__ x,
                       const float* __restrict__ ew1, const float* __restrict__ eb1,
                       const float* __restrict__ dw1, const float* __restrict__ db1)
{
    extern __shared__ float s[];
    u64* E1dp = (u64*)s;            // 4096 u64
    u64* E1sp = E1dp + 4096;        // 4096
    u64* D1p  = E1sp + 4096;        // 4096
    float* be = (float*)(D1p + 4096); // 64
    float* bd = be + 64;              // 64

    const int tid = threadIdx.x;
    const int wid = tid >> 5;
    const int lid = tid & 31;

    for (int i = tid; i < 4096; i += 512) {
        int kp = i >> 6, c = i & 63;
        E1dp[i] = pk2(ew1[(2*kp)*64 + c],        ew1[(2*kp+1)*64 + c]);
        E1sp[i] = pk2(ew1[8192 + (2*kp)*64 + c], ew1[8192 + (2*kp+1)*64 + c]);
        D1p[i]  = pk2(dw1[(2*kp)*64 + c],        dw1[(2*kp+1)*64 + c]);
    }
    if (tid < 64) { be[tid] = eb1[tid]; bd[tid] = db1[tid]; }
    __syncthreads();

    for (int base = blockIdx.x*64 + wid*4; base < NN; base += gridDim.x*64) {
        // lane holds x[n][4*lid .. 4*lid+3] as two packed pairs
        u64 xp[4][2];
        #pragma unroll
        for (int m = 0; m < 4; m++) {
            int n = (base + m < NN) ? base + m : NN - 1;
            float4 v = ((const float4*)(x + (size_t)n*DD))[lid];
            xp[m][0] = pk2(v.x, v.y);
            xp[m][1] = pk2(v.z, v.w);
        }

        u64 a[6][4];
        #pragma unroll
        for (int q = 0; q < 6; q++)
            #pragma unroll
            for (int m = 0; m < 4; m++) a[q][m] = 0ull;   // {0.f, 0.f}

        #pragma unroll 2
        for (int kq = 0; kq < 32; kq++) {
            #pragma unroll
            for (int j = 0; j < 2; j++) {
                const int kp = kq*2 + j;     // k-pair index, covers k=2kp,2kp+1
                u64 b0 = __shfl_sync(0xffffffffu, xp[0][j], kq);
                u64 b1 = __shfl_sync(0xffffffffu, xp[1][j], kq);
                u64 b2 = __shfl_sync(0xffffffffu, xp[2][j], kq);
                u64 b3 = __shfl_sync(0xffffffffu, xp[3][j], kq);
                u64 w0 = E1dp[kp*64 + lid], w1 = E1dp[kp*64 + 32 + lid];
                u64 w2 = E1sp[kp*64 + lid], w3 = E1sp[kp*64 + 32 + lid];
                u64 w4 = D1p[kp*64 + lid],  w5 = D1p[kp*64 + 32 + lid];
                fma2(a[0][0], b0, w0); fma2(a[1][0], b0, w1);
                fma2(a[2][0], b0, w2); fma2(a[3][0], b0, w3);
                fma2(a[4][0], b0, w4); fma2(a[5][0], b0, w5);
                fma2(a[0][1], b1, w0); fma2(a[1][1], b1, w1);
                fma2(a[2][1], b1, w2); fma2(a[3][1], b1, w3);
                fma2(a[4][1], b1, w4); fma2(a[5][1], b1, w5);
                fma2(a[0][2], b2, w0); fma2(a[1][2], b2, w1);
                fma2(a[2][2], b2, w2); fma2(a[3][2], b2, w3);
                fma2(a[4][2], b2, w4); fma2(a[5][2], b2, w5);
                fma2(a[0][3], b3, w0); fma2(a[1][3], b3, w1);
                fma2(a[2][3], b3, w2); fma2(a[3][3], b3, w3);
                fma2(a[4][3], b3, w4); fma2(a[5][3], b3, w5);
            }
        }

        #pragma unroll
        for (int m = 0; m < 4; m++) {
            int n = base + m;
            if (n >= NN) continue;
            size_t o = (size_t)n * 64;
            float lo, hi;
            upk2(a[0][m], lo, hi); g_hdst[o + lid]      = lo + hi + be[lid];
            upk2(a[1][m], lo, hi); g_hdst[o + 32 + lid] = lo + hi + be[32 + lid];
            upk2(a[2][m], lo, hi); g_hsrc[o + lid]      = lo + hi;
            upk2(a[3][m], lo, hi); g_hsrc[o + 32 + lid] = lo + hi;
            upk2(a[4][m], lo, hi); g_gdeg[o + lid]      = lo + hi + bd[lid];
            upk2(a[5][m], lo, hi); g_gdeg[o + 32 + lid] = lo + hi + bd[32 + lid];
        }
    }
}

// ---------------------------------------------------------------------------
// Kernel B: edge energies. Warp-task = 8 edges of one node (2 tasks/node).
// Layer-1: lane computes cols (lid, lid+32), stored packed {h[k], h[k+32]}.
// Layer-2: k-split f32x2 — per k: 2 weight LDS.64 + 8 broadcast LDS.64 +
// 16 FFMA2 (64 lane-FMA). Weights prepacked {W2[k][c], W2[k+32][c]}.
// ---------------------------------------------------------------------------
__global__ __launch_bounds__(256)
void edge_kernel(const int* __restrict__ eidx,
                 const float* __restrict__ edist,
                 const float* __restrict__ ew1,
                 const float* __restrict__ ew2, const float* __restrict__ eb2,
                 const float* __restrict__ ew3, const float* __restrict__ eb3,
                 float* __restrict__ out_e)
{
    extern __shared__ float s[];
    u64* W2p = (u64*)s;                 // 2048 u64: [k<32][64 cols]
    float* w256 = (float*)(W2p + 2048); // 64 (ew1 row 256: dist weights)
    float* b2s  = w256 + 64;            // 64
    float* W3e  = b2s + 64;             // 64
    u64* tiles  = (u64*)(W3e + 64);     // 8 warps * 256 u64

    const int tid = threadIdx.x;
    const int wid = tid >> 5;
    const int lid = tid & 31;

    for (int i = tid; i < 2048; i += 256) {
        int k = i >> 6, c = i & 63;
        W2p[i] = pk2(ew2[k*64 + c], ew2[(k+32)*64 + c]);
    }
    if (tid < 64) { w256[tid] = ew1[256*64 + tid]; b2s[tid] = eb2[tid]; W3e[tid] = ew3[tid]; }
    const float b3e = eb3[0];
    __syncthreads();

    u64* tile = tiles + wid * 256;

    for (int t = blockIdx.x*8 + wid; t < 2*NN; t += gridDim.x*8) {
        const int node  = t >> 1;
        const int ebase = (t & 1) * 8;

        const float hd0 = g_hdst[(size_t)node*64 + lid];
        const float hd1 = g_hdst[(size_t)node*64 + 32 + lid];
        const float wda = w256[lid], wdb = w256[32 + lid];

        #pragma unroll
        for (int m = 0; m < 8; m++) {
            int slot = ebase + m;
            int e    = (slot < KK) ? slot : 0;
            int src  = __ldg(eidx + node*KK + e);
            float dm = (slot < KK) ? __ldg(edist + node*KK + e) : 0.f;
            float hs0 = g_hsrc[(size_t)src*64 + lid];
            float hs1 = g_hsrc[(size_t)src*64 + 32 + lid];
            float h0 = fmaxf(fmaf(dm, wda, hd0 + hs0), 0.f);
            float h1 = fmaxf(fmaf(dm, wdb, hd1 + hs1), 0.f);
            tile[m*32 + lid] = pk2(h0, h1);     // {h[lid], h[lid+32]}
        }
        __syncwarp();

        u64 accA[8], accB[8];
        #pragma unroll
        for (int m = 0; m < 8; m++) { accA[m] = 0ull; accB[m] = 0ull; }

        #pragma unroll 2
        for (int k = 0; k < 32; k++) {
            u64 wA = W2p[k*64 + lid];
            u64 wB = W2p[k*64 + 32 + lid];
            #pragma unroll
            for (int m = 0; m < 8; m++) {
                u64 f = tile[m*32 + k];          // broadcast {h[k], h[k+32]}
                fma2(accA[m], f, wA);
                fma2(accB[m], f, wB);
            }
        }

        const float w3a = W3e[lid], w3b = W3e[32 + lid];
        const float bb0 = b2s[lid], bb1 = b2s[32 + lid];
        float p[8];
        #pragma unroll
        for (int m = 0; m < 8; m++) {
            float lo, hi;
            upk2(accA[m], lo, hi); float cA = lo + hi + bb0;
            upk2(accB[m], lo, hi); float cB = lo + hi + bb1;
            p[m] = fmaxf(cA, 0.f)*w3a + fmaxf(cB, 0.f)*w3b;
        }
        #pragma unroll
        for (int off = 16; off; off >>= 1) {
            #pragma unroll
            for (int m = 0; m < 8; m++)
                p[m] += __shfl_xor_sync(0xffffffffu, p[m], off);
        }

        float pm = p[0];
        #pragma unroll
        for (int m = 1; m < 8; m++) pm = (lid == m) ? p[m] : pm;
        if (lid < 8 && ebase + lid < KK) {
            float E = 1.f / (1.f + expf(-2.f * (pm + b3e)));  // sigmoid(logit/0.5)
            out_e[node*KK + ebase + lid] = E;
        }
        __syncwarp();
    }
}

// ---------------------------------------------------------------------------
// Kernel C: degree MLP (layer 1 precomputed, layer 2 packed f32x2) +
// rank-based hard gate + normalization. Warp per node.
// ---------------------------------------------------------------------------
__global__ __launch_bounds__(256)
void node_kernel(const float* __restrict__ dw1,
                 const float* __restrict__ dw2, const float* __restrict__ db2,
                 const float* __restrict__ dw3, const float* __restrict__ db3,
                 const float* __restrict__ energy,
                 float* __restrict__ out_w, float* __restrict__ out_g,
                 float* __restrict__ out_k)
{
    extern __shared__ float s[];
    u64* D2p = (u64*)s;                 // 2048 u64: {dw2[k][c], dw2[k+32][c]}, k<32
    float* dwh = (float*)(D2p + 2048);  // 64 (dw1 row 128: hint weights)
    float* b2d = dwh + 64;              // 64
    float* W3d = b2d + 64;              // 64
    float* es  = W3d + 64;              // 8*16
    u64* g1s   = (u64*)(es + 128);      // 8 warps * 32 u64

    const int tid = threadIdx.x;
    const int wid = tid >> 5;
    const int lid = tid & 31;

    for (int i = tid; i < 2048; i += 256) {
        int k = i >> 6, c = i & 63;
        D2p[i] = pk2(dw2[k*64 + c], dw2[(k+32)*64 + c]);
    }
    if (tid < 64) { dwh[tid] = dw1[128*64 + tid]; b2d[tid] = db2[tid]; W3d[tid] = dw3[tid]; }
    const float b3d = db3[0];
    __syncthreads();

    u64* g1 = g1s + wid * 32;

    for (int node = blockIdx.x*8 + wid; node < NN; node += gridDim.x*8) {
        float E = 0.f;
        if (lid < KK) E = energy[node*KK + lid];
        if (lid < 16) es[wid*16 + lid] = E;            // slot 15 = 0
        float hint = E;
        #pragma unroll
        for (int off = 16; off; off >>= 1) hint += __shfl_xor_sync(0xffffffffu, hint, off);

        // layer 1: lane computes cols (lid, lid+32), stores packed
        float a0 = fmaxf(fmaf(hint, dwh[lid],      g_gdeg[(size_t)node*64 + lid]),      0.f);
        float a1 = fmaxf(fmaf(hint, dwh[32 + lid], g_gdeg[(size_t)node*64 + 32 + lid]), 0.f);
        g1[lid] = pk2(a0, a1);
        __syncwarp();

        // layer 2 (64 -> 64), k-split packed
        u64 accA = 0ull, accB = 0ull;
        #pragma unroll 4
        for (int k = 0; k < 32; k++) {
            u64 f = g1[k];
            fma2(accA, f, D2p[k*64 + lid]);
            fma2(accB, f, D2p[k*64 + 32 + lid]);
        }
        float lo, hi;
        upk2(accA, lo, hi); float c0 = lo + hi + b2d[lid];
        upk2(accB, lo, hi); float c1 = lo + hi + b2d[32 + lid];

        // layer 3 + reduce -> k_cont
        float pkv = fmaxf(c0, 0.f)*W3d[lid] + fmaxf(c1, 0.f)*W3d[32 + lid];
        #pragma unroll
        for (int off = 16; off; off >>= 1) pkv += __shfl_xor_sync(0xffffffffu, pkv, off);
        const float kcont = 2.0f + 13.0f / (1.f + expf(-(pkv + b3d)));
        if (lid == 0) out_k[node] = kcont;

        // hard top-k gate via rank (stable ties by index) + normalize
        float kint = rintf(kcont);
        kint = fminf(fmaxf(kint, 2.f), 15.f);
        int cnt = 0;
        #pragma unroll
        for (int j = 0; j < KK; j++) {
            float Ej = es[wid*16 + j];
            cnt += (Ej > E) || (Ej == E && j < lid);
        }
        const float gate = ((float)(cnt + 1) <= kint) ? 1.f : 0.f;
        const float wgt  = (lid < KK) ? E * gate : 0.f;
        float denom = wgt;
        #pragma unroll
        for (int off = 16; off; off >>= 1) denom += __shfl_xor_sync(0xffffffffu, denom, off);
        denom = fmaxf(denom, 1e-12f);
        if (lid < KK) {
            out_g[node*KK + lid] = gate;
            out_w[node*KK + lid] = wgt / denom;
        }
        __syncwarp();
    }
}

extern "C" void kernel_launch(void* const* d_in, const int* in_sizes, int n_in,
                              void* d_out, int out_size)
{
    const float* x     = (const float*)d_in[0];
    const int*   eidx  = (const int*)d_in[1];    // int32 (JAX x64 disabled); row 0 = src
    const float* edist = (const float*)d_in[2];
    const float* ew1   = (const float*)d_in[3];
    const float* eb1   = (const float*)d_in[4];
    const float* ew2   = (const float*)d_in[5];
    const float* eb2   = (const float*)d_in[6];
    const float* ew3   = (const float*)d_in[7];
    const float* eb3   = (const float*)d_in[8];
    const float* dw1   = (const float*)d_in[9];
    const float* db1   = (const float*)d_in[10];
    const float* dw2   = (const float*)d_in[11];
    const float* db2   = (const float*)d_in[12];
    const float* dw3   = (const float*)d_in[13];
    const float* db3   = (const float*)d_in[14];

    float* out   = (float*)d_out;
    float* out_w = out;               // edge_weight  (N*K)
    float* out_g = out + NKE;         // edge_gate    (N*K)
    float* out_e = out + 2*NKE;       // edge_energy  (N*K)
    float* out_k = out + 3*NKE;       // k_cont       (N)

    const int smemA = 3*4096*8 + 128*4;                    //  98,816 B
    const int smemB = 2048*8 + 3*64*4 + 8*256*8;           //  33,536 B
    const int smemC = 2048*8 + (3*64 + 128)*4 + 8*32*8;    //  19,712 B
    cudaFuncSetAttribute(precompute_kernel, cudaFuncAttributeMaxDynamicSharedMemorySize, smemA);
    cudaFuncSetAttribute(edge_kernel,       cudaFuncAttributeMaxDynamicSharedMemorySize, smemB);
    cudaFuncSetAttribute(node_kernel,       cudaFuncAttributeMaxDynamicSharedMemorySize, smemC);

    precompute_kernel<<<148, 512, smemA>>>(x, ew1, eb1, dw1, db1);
    edge_kernel<<<444, 256, smemB>>>(eidx, edist, ew1, ew2, eb2, ew3, eb3, out_e);
    node_kernel<<<592, 256, smemC>>>(dw1, dw2, db2, dw3, db3, out_e, out_w, out_g, out_k);
}

// round 13
// speedup vs baseline: 1.0907x; 1.0907x over previous
#include <cuda_runtime.h>

#define NN 50000
#define KK 15
#define DD 128
#define HH 64
#define NKE (NN*KK)

typedef unsigned long long u64;

// Packed f32x2 helpers (sm_103a FFMA2 path — PTX only, ptxas never emits it).
__device__ __forceinline__ u64 pk2(float lo, float hi) {
    u64 r; asm("mov.b64 %0, {%1, %2};" : "=l"(r) : "f"(lo), "f"(hi)); return r;
}
__device__ __forceinline__ void upk2(u64 v, float& lo, float& hi) {
    asm("mov.b64 {%0, %1}, %2;" : "=f"(lo), "=f"(hi) : "l"(v));
}
__device__ __forceinline__ void fma2(u64& d, u64 a, u64 b) {
    asm("fma.rn.f32x2 %0, %1, %2, %0;" : "+l"(d) : "l"(a), "l"(b));
}

// Precomputed per-node projections (device globals — no allocation allowed).
__device__ float g_hdst[NN*64];   // x @ ew1[0:128]   + eb1
__device__ float g_hsrc[NN*64];   // x @ ew1[128:256]
__device__ float g_gdeg[NN*64];   // x @ dw1[0:128]   + db1

// ---------------------------------------------------------------------------
// Kernel A: three fused 50k x 128 @ 128x64 projections, FFMA2 + LDS.128.
// 512 threads; warp = 4 nodes, x staged in SMEM (float4 broadcast, no shfl).
// Weights packed [kp2][64 col][2] so one LDS.128 covers 4 k-steps/column.
// Per 4 k-steps: 10 LDS.128 + 48 FFMA2 (= 384 lane-FMA).
// ---------------------------------------------------------------------------
__global__ __launch_bounds__(512)
void precompute_kernel(const float* __restrict__ x,
                       const float* __restrict__ ew1, const float* __restrict__ eb1,
                       const float* __restrict__ dw1, const float* __restrict__ db1)
{
    extern __shared__ float s[];
    u64* E1dq = (u64*)s;              // 4096 u64  [32 kk][64 c][2]
    u64* E1sq = E1dq + 4096;          // 4096
    u64* D1q  = E1sq + 4096;          // 4096
    float* be = (float*)(D1q + 4096); // 64
    float* bd = be + 64;              // 64
    float* xs = bd + 64;              // 16 warps * 512 floats

    const int tid = threadIdx.x;
    const int wid = tid >> 5;
    const int lid = tid & 31;

    // pack: [kk][c][h] holds {W[4kk+2h][c], W[4kk+2h+1][c]}
    for (int i = tid; i < 4096; i += 512) {
        int kk = i >> 7, r = i & 127, c = r >> 1, h = r & 1;
        int k0 = 4*kk + 2*h;
        E1dq[i] = pk2(ew1[k0*64 + c],        ew1[(k0+1)*64 + c]);
        E1sq[i] = pk2(ew1[8192 + k0*64 + c], ew1[8192 + (k0+1)*64 + c]);
        D1q[i]  = pk2(dw1[k0*64 + c],        dw1[(k0+1)*64 + c]);
    }
    if (tid < 64) { be[tid] = eb1[tid]; bd[tid] = db1[tid]; }
    __syncthreads();

    float* xw = xs + wid * 512;

    for (int base = blockIdx.x*64 + wid*4; base < NN; base += gridDim.x*64) {
        #pragma unroll
        for (int m = 0; m < 4; m++) {
            int n = (base + m < NN) ? base + m : NN - 1;
            ((float4*)(xw + m*128))[lid] = ((const float4*)(x + (size_t)n*DD))[lid];
        }
        __syncwarp();

        u64 a[6][4];
        #pragma unroll
        for (int q = 0; q < 6; q++)
            #pragma unroll
            for (int m = 0; m < 4; m++) a[q][m] = 0ull;

        #pragma unroll 2
        for (int kk = 0; kk < 32; kk++) {         // covers k = 4kk .. 4kk+3
            u64 bx[4][2];
            #pragma unroll
            for (int m = 0; m < 4; m++) {
                float4 xv = *(const float4*)(xw + m*128 + kk*4);
                bx[m][0] = pk2(xv.x, xv.y);
                bx[m][1] = pk2(xv.z, xv.w);
            }
            const u64* p0 = E1dq + kk*128;
            const u64* p1 = E1sq + kk*128;
            const u64* p2 = D1q  + kk*128;
            ulonglong2 w0 = *(const ulonglong2*)(p0 + 2*lid);
            ulonglong2 w1 = *(const ulonglong2*)(p0 + 64 + 2*lid);
            ulonglong2 w2 = *(const ulonglong2*)(p1 + 2*lid);
            ulonglong2 w3 = *(const ulonglong2*)(p1 + 64 + 2*lid);
            ulonglong2 w4 = *(const ulonglong2*)(p2 + 2*lid);
            ulonglong2 w5 = *(const ulonglong2*)(p2 + 64 + 2*lid);
            #pragma unroll
            for (int m = 0; m < 4; m++) {
                fma2(a[0][m], bx[m][0], w0.x); fma2(a[0][m], bx[m][1], w0.y);
                fma2(a[1][m], bx[m][0], w1.x); fma2(a[1][m], bx[m][1], w1.y);
                fma2(a[2][m], bx[m][0], w2.x); fma2(a[2][m], bx[m][1], w2.y);
                fma2(a[3][m], bx[m][0], w3.x); fma2(a[3][m], bx[m][1], w3.y);
                fma2(a[4][m], bx[m][0], w4.x); fma2(a[4][m], bx[m][1], w4.y);
                fma2(a[5][m], bx[m][0], w5.x); fma2(a[5][m], bx[m][1], w5.y);
            }
        }

        #pragma unroll
        for (int m = 0; m < 4; m++) {
            int n = base + m;
            if (n >= NN) continue;
            size_t o = (size_t)n * 64;
            float lo, hi;
            upk2(a[0][m], lo, hi); g_hdst[o + lid]      = lo + hi + be[lid];
            upk2(a[1][m], lo, hi); g_hdst[o + 32 + lid] = lo + hi + be[32 + lid];
            upk2(a[2][m], lo, hi); g_hsrc[o + lid]      = lo + hi;
            upk2(a[3][m], lo, hi); g_hsrc[o + 32 + lid] = lo + hi;
            upk2(a[4][m], lo, hi); g_gdeg[o + lid]      = lo + hi + bd[lid];
            upk2(a[5][m], lo, hi); g_gdeg[o + 32 + lid] = lo + hi + bd[32 + lid];
        }
        __syncwarp();
    }
}

// ---------------------------------------------------------------------------
// Kernel B: edge energies. Warp-task = 8 edges of one node.
// Layer-2 weights packed [k2][64 c][2]: one LDS.128 = 2 k-steps of f32x2
// weights; tile broadcasts also LDS.128. Per 2 k: 10 LDS.128 + 32 FFMA2.
// ---------------------------------------------------------------------------
__global__ __launch_bounds__(256)
void edge_kernel(const int* __restrict__ eidx,
                 const float* __restrict__ edist,
                 const float* __restrict__ ew1,
                 const float* __restrict__ ew2, const float* __restrict__ eb2,
                 const float* __restrict__ ew3, const float* __restrict__ eb3,
                 float* __restrict__ out_e)
{
    extern __shared__ float s[];
    u64* W2q = (u64*)s;                 // 2048 u64  [16 k2][64 c][2]
    float* w256 = (float*)(W2q + 2048); // 64 (ew1 row 256: dist weights)
    float* b2s  = w256 + 64;            // 64
    float* W3e  = b2s + 64;             // 64
    u64* tiles  = (u64*)(W3e + 64);     // 8 warps * 256 u64

    const int tid = threadIdx.x;
    const int wid = tid >> 5;
    const int lid = tid & 31;

    // pack: [k2][c][h] holds {W2[2k2+h][c], W2[2k2+h+32][c]}
    for (int i = tid; i < 2048; i += 256) {
        int k2 = i >> 7, r = i & 127, c = r >> 1, h = r & 1;
        int k = 2*k2 + h;
        W2q[i] = pk2(ew2[k*64 + c], ew2[(k+32)*64 + c]);
    }
    if (tid < 64) { w256[tid] = ew1[256*64 + tid]; b2s[tid] = eb2[tid]; W3e[tid] = ew3[tid]; }
    const float b3e = eb3[0];
    __syncthreads();

    u64* tile = tiles + wid * 256;

    for (int t = blockIdx.x*8 + wid; t < 2*NN; t += gridDim.x*8) {
        const int node  = t >> 1;
        const int ebase = (t & 1) * 8;

        const float hd0 = g_hdst[(size_t)node*64 + lid];
        const float hd1 = g_hdst[(size_t)node*64 + 32 + lid];
        const float wda = w256[lid], wdb = w256[32 + lid];

        #pragma unroll
        for (int m = 0; m < 8; m++) {
            int slot = ebase + m;
            int e    = (slot < KK) ? slot : 0;
            int src  = __ldg(eidx + node*KK + e);
            float dm = (slot < KK) ? __ldg(edist + node*KK + e) : 0.f;
            float hs0 = g_hsrc[(size_t)src*64 + lid];
            float hs1 = g_hsrc[(size_t)src*64 + 32 + lid];
            float h0 = fmaxf(fmaf(dm, wda, hd0 + hs0), 0.f);
            float h1 = fmaxf(fmaf(dm, wdb, hd1 + hs1), 0.f);
            tile[m*32 + lid] = pk2(h0, h1);     // {h[lid], h[lid+32]}
        }
        __syncwarp();

        u64 accA[8], accB[8];
        #pragma unroll
        for (int m = 0; m < 8; m++) { accA[m] = 0ull; accB[m] = 0ull; }

        #pragma unroll 2
        for (int k2 = 0; k2 < 16; k2++) {        // covers k = 2k2, 2k2+1
            const u64* wr = W2q + k2*128;
            ulonglong2 wa = *(const ulonglong2*)(wr + 2*lid);
            ulonglong2 wb = *(const ulonglong2*)(wr + 64 + 2*lid);
            #pragma unroll
            for (int m = 0; m < 8; m++) {
                ulonglong2 f = *(const ulonglong2*)(tile + m*32 + 2*k2);
                fma2(accA[m], f.x, wa.x); fma2(accA[m], f.y, wa.y);
                fma2(accB[m], f.x, wb.x); fma2(accB[m], f.y, wb.y);
            }
        }

        const float w3a = W3e[lid], w3b = W3e[32 + lid];
        const float bb0 = b2s[lid], bb1 = b2s[32 + lid];
        float p[8];
        #pragma unroll
        for (int m = 0; m < 8; m++) {
            float lo, hi;
            upk2(accA[m], lo, hi); float cA = lo + hi + bb0;
            upk2(accB[m], lo, hi); float cB = lo + hi + bb1;
            p[m] = fmaxf(cA, 0.f)*w3a + fmaxf(cB, 0.f)*w3b;
        }
        #pragma unroll
        for (int off = 16; off; off >>= 1) {
            #pragma unroll
            for (int m = 0; m < 8; m++)
                p[m] += __shfl_xor_sync(0xffffffffu, p[m], off);
        }

        float pm = p[0];
        #pragma unroll
        for (int m = 1; m < 8; m++) pm = (lid == m) ? p[m] : pm;
        if (lid < 8 && ebase + lid < KK) {
            float E = 1.f / (1.f + expf(-2.f * (pm + b3e)));  // sigmoid(logit/0.5)
            out_e[node*KK + ebase + lid] = E;
        }
        __syncwarp();
    }
}

// ---------------------------------------------------------------------------
// Kernel C: degree MLP (layer 1 precomputed, layer 2 FFMA2 + LDS.128) +
// rank-based hard gate + normalization. Warp per node.
// ---------------------------------------------------------------------------
__global__ __launch_bounds__(256)
void node_kernel(const float* __restrict__ dw1,
                 const float* __restrict__ dw2, const float* __restrict__ db2,
                 const float* __restrict__ dw3, const float* __restrict__ db3,
                 const float* __restrict__ energy,
                 float* __restrict__ out_w, float* __restrict__ out_g,
                 float* __restrict__ out_k)
{
    extern __shared__ float s[];
    u64* D2q = (u64*)s;                 // 2048 u64  [16 k2][64 c][2]
    float* dwh = (float*)(D2q + 2048);  // 64 (dw1 row 128: hint weights)
    float* b2d = dwh + 64;              // 64
    float* W3d = b2d + 64;              // 64
    float* es  = W3d + 64;              // 8*16
    u64* g1s   = (u64*)(es + 128);      // 8 warps * 32 u64

    const int tid = threadIdx.x;
    const int wid = tid >> 5;
    const int lid = tid & 31;

    for (int i = tid; i < 2048; i += 256) {
        int k2 = i >> 7, r = i & 127, c = r >> 1, h = r & 1;
        int k = 2*k2 + h;
        D2q[i] = pk2(dw2[k*64 + c], dw2[(k+32)*64 + c]);
    }
    if (tid < 64) { dwh[tid] = dw1[128*64 + tid]; b2d[tid] = db2[tid]; W3d[tid] = dw3[tid]; }
    const float b3d = db3[0];
    __syncthreads();

    u64* g1 = g1s + wid * 32;

    for (int node = blockIdx.x*8 + wid; node < NN; node += gridDim.x*8) {
        float E = 0.f;
        if (lid < KK) E = energy[node*KK + lid];
        if (lid < 16) es[wid*16 + lid] = E;            // slot 15 = 0
        float hint = E;
        #pragma unroll
        for (int off = 16; off; off >>= 1) hint += __shfl_xor_sync(0xffffffffu, hint, off);

        // layer 1: lane computes cols (lid, lid+32), stores packed
        float a0 = fmaxf(fmaf(hint, dwh[lid],      g_gdeg[(size_t)node*64 + lid]),      0.f);
        float a1 = fmaxf(fmaf(hint, dwh[32 + lid], g_gdeg[(size_t)node*64 + 32 + lid]), 0.f);
        g1[lid] = pk2(a0, a1);
        __syncwarp();

        // layer 2 (64 -> 64), k-split packed, LDS.128
        u64 accA = 0ull, accB = 0ull;
        #pragma unroll 4
        for (int k2 = 0; k2 < 16; k2++) {
            const u64* wr = D2q + k2*128;
            ulonglong2 wa = *(const ulonglong2*)(wr + 2*lid);
            ulonglong2 wb = *(const ulonglong2*)(wr + 64 + 2*lid);
            ulonglong2 f  = *(const ulonglong2*)(g1 + 2*k2);
            fma2(accA, f.x, wa.x); fma2(accA, f.y, wa.y);
            fma2(accB, f.x, wb.x); fma2(accB, f.y, wb.y);
        }
        float lo, hi;
        upk2(accA, lo, hi); float c0 = lo + hi + b2d[lid];
        upk2(accB, lo, hi); float c1 = lo + hi + b2d[32 + lid];

        // layer 3 + reduce -> k_cont
        float pkv = fmaxf(c0, 0.f)*W3d[lid] + fmaxf(c1, 0.f)*W3d[32 + lid];
        #pragma unroll
        for (int off = 16; off; off >>= 1) pkv += __shfl_xor_sync(0xffffffffu, pkv, off);
        const float kcont = 2.0f + 13.0f / (1.f + expf(-(pkv + b3d)));
        if (lid == 0) out_k[node] = kcont;

        // hard top-k gate via rank (stable ties by index) + normalize
        float kint = rintf(kcont);
        kint = fminf(fmaxf(kint, 2.f), 15.f);
        int cnt = 0;
        #pragma unroll
        for (int j = 0; j < KK; j++) {
            float Ej = es[wid*16 + j];
            cnt += (Ej > E) || (Ej == E && j < lid);
        }
        const float gate = ((float)(cnt + 1) <= kint) ? 1.f : 0.f;
        const float wgt  = (lid < KK) ? E * gate : 0.f;
        float denom = wgt;
        #pragma unroll
        for (int off = 16; off; off >>= 1) denom += __shfl_xor_sync(0xffffffffu, denom, off);
        denom = fmaxf(denom, 1e-12f);
        if (lid < KK) {
            out_g[node*KK + lid] = gate;
            out_w[node*KK + lid] = wgt / denom;
        }
        __syncwarp();
    }
}

extern "C" void kernel_launch(void* const* d_in, const int* in_sizes, int n_in,
                              void* d_out, int out_size)
{
    const float* x     = (const float*)d_in[0];
    const int*   eidx  = (const int*)d_in[1];    // int32 (JAX x64 disabled); row 0 = src
    const float* edist = (const float*)d_in[2];
    const float* ew1   = (const float*)d_in[3];
    const float* eb1   = (const float*)d_in[4];
    const float* ew2   = (const float*)d_in[5];
    const float* eb2   = (const float*)d_in[6];
    const float* ew3   = (const float*)d_in[7];
    const float* eb3   = (const float*)d_in[8];
    const float* dw1   = (const float*)d_in[9];
    const float* db1   = (const float*)d_in[10];
    const float* dw2   = (const float*)d_in[11];
    const float* db2   = (const float*)d_in[12];
    const float* dw3   = (const float*)d_in[13];
    const float* db3   = (const float*)d_in[14];

    float* out   = (float*)d_out;
    float* out_w = out;               // edge_weight  (N*K)
    float* out_g = out + NKE;         // edge_gate    (N*K)
    float* out_e = out + 2*NKE;       // edge_energy  (N*K)
    float* out_k = out + 3*NKE;       // k_cont       (N)

    const int smemA = 3*4096*8 + 128*4 + 16*512*4;         // 131,584 B
    const int smemB = 2048*8 + 3*64*4 + 8*256*8;           //  33,536 B
    const int smemC = 2048*8 + (3*64 + 128)*4 + 8*32*8;    //  19,712 B
    cudaFuncSetAttribute(precompute_kernel, cudaFuncAttributeMaxDynamicSharedMemorySize, smemA);
    cudaFuncSetAttribute(edge_kernel,       cudaFuncAttributeMaxDynamicSharedMemorySize, smemB);
    cudaFuncSetAttribute(node_kernel,       cudaFuncAttributeMaxDynamicSharedMemorySize, smemC);

    precompute_kernel<<<148, 512, smemA>>>(x, ew1, eb1, dw1, db1);
    edge_kernel<<<444, 256, smemB>>>(eidx, edist, ew1, ew2, eb2, ew3, eb3, out_e);
    node_kernel<<<592, 256, smemC>>>(dw1, dw2, db2, dw3, db3, out_e, out_w, out_g, out_k);
}

// round 14
// speedup vs baseline: 1.1355x; 1.0411x over previous
#include <cuda_runtime.h>

#define NN 50000
#define KK 15
#define DD 128
#define HH 64
#define NKE (NN*KK)

typedef unsigned long long u64;

// Packed f32x2 helpers (sm_103a FFMA2 path — PTX only, ptxas never emits it).
__device__ __forceinline__ u64 pk2(float lo, float hi) {
    u64 r; asm("mov.b64 %0, {%1, %2};" : "=l"(r) : "f"(lo), "f"(hi)); return r;
}
__device__ __forceinline__ void upk2(u64 v, float& lo, float& hi) {
    asm("mov.b64 {%0, %1}, %2;" : "=f"(lo), "=f"(hi) : "l"(v));
}
__device__ __forceinline__ void fma2(u64& d, u64 a, u64 b) {
    asm("fma.rn.f32x2 %0, %1, %2, %0;" : "+l"(d) : "l"(a), "l"(b));
}

// Precomputed per-node projections (device globals — no allocation allowed).
__device__ float g_hdst[NN*64];   // x @ ew1[0:128]   + eb1
__device__ float g_hsrc[NN*64];   // x @ ew1[128:256]
__device__ float g_gdeg[NN*64];   // x @ dw1[0:128]   + db1

// ---------------------------------------------------------------------------
// Kernel A: three fused 50k x 128 @ 128x64 projections, FFMA2 + LDS.128.
// 512 threads (16 warps, 1 block/SM); warp = 6 nodes (weight reads amortized
// over 6 rows: 160 crossbar phases/node vs 224 at m=4).
// Per 4 k-steps: 6 weight LDS.128 (4 phases) + 6 bcast LDS.128 (1 phase)
// + 36 FFMA2 (= 288 lane-FMA).
// ---------------------------------------------------------------------------
__global__ __launch_bounds__(512)
void precompute_kernel(const float* __restrict__ x,
                       const float* __restrict__ ew1, const float* __restrict__ eb1,
                       const float* __restrict__ dw1, const float* __restrict__ db1)
{
    extern __shared__ float s[];
    u64* E1dq = (u64*)s;              // 4096 u64  [32 kk][64 c][2]
    u64* E1sq = E1dq + 4096;          // 4096
    u64* D1q  = E1sq + 4096;          // 4096
    float* be = (float*)(D1q + 4096); // 64
    float* bd = be + 64;              // 64
    float* xs = bd + 64;              // 16 warps * 768 floats

    const int tid = threadIdx.x;
    const int wid = tid >> 5;
    const int lid = tid & 31;

    // pack: [kk][c][h] holds {W[4kk+2h][c], W[4kk+2h+1][c]}
    for (int i = tid; i < 4096; i += 512) {
        int kk = i >> 7, r = i & 127, c = r >> 1, h = r & 1;
        int k0 = 4*kk + 2*h;
        E1dq[i] = pk2(ew1[k0*64 + c],        ew1[(k0+1)*64 + c]);
        E1sq[i] = pk2(ew1[8192 + k0*64 + c], ew1[8192 + (k0+1)*64 + c]);
        D1q[i]  = pk2(dw1[k0*64 + c],        dw1[(k0+1)*64 + c]);
    }
    if (tid < 64) { be[tid] = eb1[tid]; bd[tid] = db1[tid]; }
    __syncthreads();

    float* xw = xs + wid * 768;

    for (int base = blockIdx.x*96 + wid*6; base < NN; base += gridDim.x*96) {
        #pragma unroll
        for (int m = 0; m < 6; m++) {
            int n = base + m;
            n = (n < NN) ? n : NN - 1;
            ((float4*)(xw + m*128))[lid] = ((const float4*)(x + (size_t)n*DD))[lid];
        }
        __syncwarp();

        u64 a[6][6];                      // [q][m]
        #pragma unroll
        for (int q = 0; q < 6; q++)
            #pragma unroll
            for (int m = 0; m < 6; m++) a[q][m] = 0ull;

        #pragma unroll 2
        for (int kk = 0; kk < 32; kk++) {             // covers k = 4kk .. 4kk+3
            const u64* p0 = E1dq + kk*128;
            const u64* p1 = E1sq + kk*128;
            const u64* p2 = D1q  + kk*128;
            ulonglong2 w0 = *(const ulonglong2*)(p0 + 2*lid);
            ulonglong2 w1 = *(const ulonglong2*)(p0 + 64 + 2*lid);
            ulonglong2 w2 = *(const ulonglong2*)(p1 + 2*lid);
            ulonglong2 w3 = *(const ulonglong2*)(p1 + 64 + 2*lid);
            ulonglong2 w4 = *(const ulonglong2*)(p2 + 2*lid);
            ulonglong2 w5 = *(const ulonglong2*)(p2 + 64 + 2*lid);
            #pragma unroll
            for (int m = 0; m < 6; m++) {
                float4 xv = *(const float4*)(xw + m*128 + kk*4);
                u64 blo = pk2(xv.x, xv.y);
                u64 bhi = pk2(xv.z, xv.w);
                fma2(a[0][m], blo, w0.x); fma2(a[0][m], bhi, w0.y);
                fma2(a[1][m], blo, w1.x); fma2(a[1][m], bhi, w1.y);
                fma2(a[2][m], blo, w2.x); fma2(a[2][m], bhi, w2.y);
                fma2(a[3][m], blo, w3.x); fma2(a[3][m], bhi, w3.y);
                fma2(a[4][m], blo, w4.x); fma2(a[4][m], bhi, w4.y);
                fma2(a[5][m], blo, w5.x); fma2(a[5][m], bhi, w5.y);
            }
        }

        #pragma unroll
        for (int m = 0; m < 6; m++) {
            int n = base + m;
            if (n >= NN) continue;
            size_t o = (size_t)n * 64;
            float lo, hi;
            upk2(a[0][m], lo, hi); g_hdst[o + lid]      = lo + hi + be[lid];
            upk2(a[1][m], lo, hi); g_hdst[o + 32 + lid] = lo + hi + be[32 + lid];
            upk2(a[2][m], lo, hi); g_hsrc[o + lid]      = lo + hi;
            upk2(a[3][m], lo, hi); g_hsrc[o + 32 + lid] = lo + hi;
            upk2(a[4][m], lo, hi); g_gdeg[o + lid]      = lo + hi + bd[lid];
            upk2(a[5][m], lo, hi); g_gdeg[o + 32 + lid] = lo + hi + bd[32 + lid];
        }
        __syncwarp();
    }
}

// ---------------------------------------------------------------------------
// Kernel B: edge energies. Warp = ONE NODE (all 15 edges): W2 read once per
// node instead of twice. Per k2: 2 weight LDS.128 (8 phases) + 15 broadcast
// LDS.128 (15 phases) + 60 FFMA2.
// ---------------------------------------------------------------------------
__global__ __launch_bounds__(256, 2)
void edge_kernel(const int* __restrict__ eidx,
                 const float* __restrict__ edist,
                 const float* __restrict__ ew1,
                 const float* __restrict__ ew2, const float* __restrict__ eb2,
                 const float* __restrict__ ew3, const float* __restrict__ eb3,
                 float* __restrict__ out_e)
{
    extern __shared__ float s[];
    u64* W2q = (u64*)s;                 // 2048 u64  [16 k2][64 c][2]
    float* w256 = (float*)(W2q + 2048); // 64 (ew1 row 256: dist weights)
    float* b2s  = w256 + 64;            // 64
    float* W3e  = b2s + 64;             // 64
    u64* tiles  = (u64*)(W3e + 64);     // 8 warps * 512 u64

    const int tid = threadIdx.x;
    const int wid = tid >> 5;
    const int lid = tid & 31;

    // pack: [k2][c][h] holds {W2[2k2+h][c], W2[2k2+h+32][c]}
    for (int i = tid; i < 2048; i += 256) {
        int k2 = i >> 7, r = i & 127, c = r >> 1, h = r & 1;
        int k = 2*k2 + h;
        W2q[i] = pk2(ew2[k*64 + c], ew2[(k+32)*64 + c]);
    }
    if (tid < 64) { w256[tid] = ew1[256*64 + tid]; b2s[tid] = eb2[tid]; W3e[tid] = ew3[tid]; }
    const float b3e = eb3[0];
    __syncthreads();

    u64* tile = tiles + wid * 512;

    for (int node = blockIdx.x*8 + wid; node < NN; node += gridDim.x*8) {
        const float hd0 = g_hdst[(size_t)node*64 + lid];
        const float hd1 = g_hdst[(size_t)node*64 + 32 + lid];
        const float wda = w256[lid], wdb = w256[32 + lid];

        #pragma unroll
        for (int m = 0; m < KK; m++) {
            int src  = __ldg(eidx + node*KK + m);
            float dm = __ldg(edist + node*KK + m);
            float hs0 = g_hsrc[(size_t)src*64 + lid];
            float hs1 = g_hsrc[(size_t)src*64 + 32 + lid];
            float h0 = fmaxf(fmaf(dm, wda, hd0 + hs0), 0.f);
            float h1 = fmaxf(fmaf(dm, wdb, hd1 + hs1), 0.f);
            tile[m*32 + lid] = pk2(h0, h1);     // {h[lid], h[lid+32]}
        }
        __syncwarp();

        u64 accA[KK], accB[KK];
        #pragma unroll
        for (int m = 0; m < KK; m++) { accA[m] = 0ull; accB[m] = 0ull; }

        #pragma unroll 2
        for (int k2 = 0; k2 < 16; k2++) {        // covers k = 2k2, 2k2+1 (+32)
            const u64* wr = W2q + k2*128;
            ulonglong2 wa = *(const ulonglong2*)(wr + 2*lid);
            ulonglong2 wb = *(const ulonglong2*)(wr + 64 + 2*lid);
            #pragma unroll
            for (int m = 0; m < KK; m++) {
                ulonglong2 f = *(const ulonglong2*)(tile + m*32 + 2*k2);
                fma2(accA[m], f.x, wa.x); fma2(accA[m], f.y, wa.y);
                fma2(accB[m], f.x, wb.x); fma2(accB[m], f.y, wb.y);
            }
        }

        const float w3a = W3e[lid], w3b = W3e[32 + lid];
        const float bb0 = b2s[lid], bb1 = b2s[32 + lid];
        float p[KK];
        #pragma unroll
        for (int m = 0; m < KK; m++) {
            float lo, hi;
            upk2(accA[m], lo, hi); float cA = lo + hi + bb0;
            upk2(accB[m], lo, hi); float cB = lo + hi + bb1;
            p[m] = fmaxf(cA, 0.f)*w3a + fmaxf(cB, 0.f)*w3b;
        }
        #pragma unroll
        for (int off = 16; off; off >>= 1) {
            #pragma unroll
            for (int m = 0; m < KK; m++)
                p[m] += __shfl_xor_sync(0xffffffffu, p[m], off);
        }

        float pm = p[0];
        #pragma unroll
        for (int m = 1; m < KK; m++) pm = (lid == m) ? p[m] : pm;
        if (lid < KK) {
            float E = 1.f / (1.f + expf(-2.f * (pm + b3e)));  // sigmoid(logit/0.5)
            out_e[node*KK + lid] = E;
        }
        __syncwarp();
    }
}

// ---------------------------------------------------------------------------
// Kernel C: degree MLP + rank gate, FOUR nodes per warp (D2 weight reads
// amortized 4x: 48 crossbar phases/node vs 144).
// ---------------------------------------------------------------------------
__global__ __launch_bounds__(256)
void node_kernel(const float* __restrict__ dw1,
                 const float* __restrict__ dw2, const float* __restrict__ db2,
                 const float* __restrict__ dw3, const float* __restrict__ db3,
                 const float* __restrict__ energy,
                 float* __restrict__ out_w, float* __restrict__ out_g,
                 float* __restrict__ out_k)
{
    extern __shared__ float s[];
    u64* D2q = (u64*)s;                 // 2048 u64  [16 k2][64 c][2]
    float* dwh = (float*)(D2q + 2048);  // 64 (dw1 row 128: hint weights)
    float* b2d = dwh + 64;              // 64
    float* W3d = b2d + 64;              // 64
    float* es  = W3d + 64;              // 8 warps * 64  (4 nodes x 16)
    u64* g1s   = (u64*)(es + 512);      // 8 warps * 128 u64 (4 nodes x 32)

    const int tid = threadIdx.x;
    const int wid = tid >> 5;
    const int lid = tid & 31;

    for (int i = tid; i < 2048; i += 256) {
        int k2 = i >> 7, r = i & 127, c = r >> 1, h = r & 1;
        int k = 2*k2 + h;
        D2q[i] = pk2(dw2[k*64 + c], dw2[(k+32)*64 + c]);
    }
    if (tid < 64) { dwh[tid] = dw1[128*64 + tid]; b2d[tid] = db2[tid]; W3d[tid] = dw3[tid]; }
    const float b3d = db3[0];
    __syncthreads();

    u64* g1    = g1s + wid * 128;
    float* esw = es + wid * 64;

    for (int base = blockIdx.x*32 + wid*4; base < NN; base += gridDim.x*32) {
        int n[4];
        float Ej[4];
        #pragma unroll
        for (int j = 0; j < 4; j++) {
            n[j] = (base + j < NN) ? base + j : NN - 1;
            float E = (lid < KK) ? energy[n[j]*KK + lid] : 0.f;
            Ej[j] = E;
            if (lid < 16) esw[j*16 + lid] = E;     // slot 15 = 0
            float hint = E;
            #pragma unroll
            for (int off = 16; off; off >>= 1) hint += __shfl_xor_sync(0xffffffffu, hint, off);
            // layer 1: lane computes cols (lid, lid+32), stores packed
            float a0 = fmaxf(fmaf(hint, dwh[lid],      g_gdeg[(size_t)n[j]*64 + lid]),      0.f);
            float a1 = fmaxf(fmaf(hint, dwh[32 + lid], g_gdeg[(size_t)n[j]*64 + 32 + lid]), 0.f);
            g1[j*32 + lid] = pk2(a0, a1);
        }
        __syncwarp();

        // layer 2 (64 -> 64) for 4 nodes, weights read once
        u64 accA[4], accB[4];
        #pragma unroll
        for (int j = 0; j < 4; j++) { accA[j] = 0ull; accB[j] = 0ull; }
        #pragma unroll 2
        for (int k2 = 0; k2 < 16; k2++) {
            const u64* wr = D2q + k2*128;
            ulonglong2 wa = *(const ulonglong2*)(wr + 2*lid);
            ulonglong2 wb = *(const ulonglong2*)(wr + 64 + 2*lid);
            #pragma unroll
            for (int j = 0; j < 4; j++) {
                ulonglong2 f = *(const ulonglong2*)(g1 + j*32 + 2*k2);
                fma2(accA[j], f.x, wa.x); fma2(accA[j], f.y, wa.y);
                fma2(accB[j], f.x, wb.x); fma2(accB[j], f.y, wb.y);
            }
        }

        #pragma unroll
        for (int j = 0; j < 4; j++) {
            float lo, hi;
            upk2(accA[j], lo, hi); float c0 = lo + hi + b2d[lid];
            upk2(accB[j], lo, hi); float c1 = lo + hi + b2d[32 + lid];
            float pkv = fmaxf(c0, 0.f)*W3d[lid] + fmaxf(c1, 0.f)*W3d[32 + lid];
            #pragma unroll
            for (int off = 16; off; off >>= 1) pkv += __shfl_xor_sync(0xffffffffu, pkv, off);
            const float kcont = 2.0f + 13.0f / (1.f + expf(-(pkv + b3d)));
            const bool valid = (base + j < NN);
            if (lid == 0 && valid) out_k[n[j]] = kcont;

            // hard top-k gate via rank (stable ties by index) + normalize
            float kint = rintf(kcont);
            kint = fminf(fmaxf(kint, 2.f), 15.f);
            float E = Ej[j];
            int cnt = 0;
            #pragma unroll
            for (int jj = 0; jj < KK; jj++) {
                float Ex = esw[j*16 + jj];
                cnt += (Ex > E) || (Ex == E && jj < lid);
            }
            const float gate = ((float)(cnt + 1) <= kint) ? 1.f : 0.f;
            const float wgt  = (lid < KK) ? E * gate : 0.f;
            float denom = wgt;
            #pragma unroll
            for (int off = 16; off; off >>= 1) denom += __shfl_xor_sync(0xffffffffu, denom, off);
            denom = fmaxf(denom, 1e-12f);
            if (lid < KK && valid) {
                out_g[n[j]*KK + lid] = gate;
                out_w[n[j]*KK + lid] = wgt / denom;
            }
        }
        __syncwarp();
    }
}

extern "C" void kernel_launch(void* const* d_in, const int* in_sizes, int n_in,
                              void* d_out, int out_size)
{
    const float* x     = (const float*)d_in[0];
    const int*   eidx  = (const int*)d_in[1];    // int32 (JAX x64 disabled); row 0 = src
    const float* edist = (const float*)d_in[2];
    const float* ew1   = (const float*)d_in[3];
    const float* eb1   = (const float*)d_in[4];
    const float* ew2   = (const float*)d_in[5];
    const float* eb2   = (const float*)d_in[6];
    const float* ew3   = (const float*)d_in[7];
    const float* eb3   = (const float*)d_in[8];
    const float* dw1   = (const float*)d_in[9];
    const float* db1   = (const float*)d_in[10];
    const float* dw2   = (const float*)d_in[11];
    const float* db2   = (const float*)d_in[12];
    const float* dw3   = (const float*)d_in[13];
    const float* db3   = (const float*)d_in[14];

    float* out   = (float*)d_out;
    float* out_w = out;               // edge_weight  (N*K)
    float* out_g = out + NKE;         // edge_gate    (N*K)
    float* out_e = out + 2*NKE;       // edge_energy  (N*K)
    float* out_k = out + 3*NKE;       // k_cont       (N)

    const int smemA = 3*4096*8 + 128*4 + 16*768*4;         // 147,968 B
    const int smemB = 2048*8 + 192*4 + 8*512*8;            //  49,920 B
    const int smemC = 2048*8 + 192*4 + 512*4 + 8*128*8;    //  27,392 B
    cudaFuncSetAttribute(precompute_kernel, cudaFuncAttributeMaxDynamicSharedMemorySize, smemA);
    cudaFuncSetAttribute(edge_kernel,       cudaFuncAttributeMaxDynamicSharedMemorySize, smemB);
    cudaFuncSetAttribute(node_kernel,       cudaFuncAttributeMaxDynamicSharedMemorySize, smemC);

    precompute_kernel<<<148, 512, smemA>>>(x, ew1, eb1, dw1, db1);
    edge_kernel<<<296, 256, smemB>>>(eidx, edist, ew1, ew2, eb2, ew3, eb3, out_e);
    node_kernel<<<296, 256, smemC>>>(dw1, dw2, db2, dw3, db3, out_e, out_w, out_g, out_k);
}

// round 15
// speedup vs baseline: 1.1366x; 1.0010x over previous
#include <cuda_runtime.h>

#define NN 50000
#define KK 15
#define DD 128
#define HH 64
#define NKE (NN*KK)

typedef unsigned long long u64;

// Packed f32x2 helpers (sm_103a FFMA2 path — PTX only, ptxas never emits it).
__device__ __forceinline__ u64 pk2(float lo, float hi) {
    u64 r; asm("mov.b64 %0, {%1, %2};" : "=l"(r) : "f"(lo), "f"(hi)); return r;
}
__device__ __forceinline__ void upk2(u64 v, float& lo, float& hi) {
    asm("mov.b64 {%0, %1}, %2;" : "=f"(lo), "=f"(hi) : "l"(v));
}
__device__ __forceinline__ void fma2(u64& d, u64 a, u64 b) {
    asm("fma.rn.f32x2 %0, %1, %2, %0;" : "+l"(d) : "l"(a), "l"(b));
}

// Precomputed per-node projections (device globals — no allocation allowed).
__device__ float g_hdst[NN*64];   // x @ ew1[0:128]   + eb1
__device__ float g_hsrc[NN*64];   // x @ ew1[128:256]
__device__ float g_gdeg[NN*64];   // x @ dw1[0:128]   + db1

// ---------------------------------------------------------------------------
// Kernel A: three fused 50k x 128 @ 128x64 projections, FFMA2 + LDS.128.
// 512 threads (16 warps, 1 block/SM); warp = 6 nodes (weight reads amortized
// over 6 rows: 160 crossbar phases/node vs 224 at m=4).
// Per 4 k-steps: 6 weight LDS.128 (4 phases) + 6 bcast LDS.128 (1 phase)
// + 36 FFMA2 (= 288 lane-FMA).
// ---------------------------------------------------------------------------
__global__ __launch_bounds__(512)
void precompute_kernel(const float* __restrict__ x,
                       const float* __restrict__ ew1, const float* __restrict__ eb1,
                       const float* __restrict__ dw1, const float* __restrict__ db1)
{
    extern __shared__ float s[];
    u64* E1dq = (u64*)s;              // 4096 u64  [32 kk][64 c][2]
    u64* E1sq = E1dq + 4096;          // 4096
    u64* D1q  = E1sq + 4096;          // 4096
    float* be = (float*)(D1q + 4096); // 64
    float* bd = be + 64;              // 64
    float* xs = bd + 64;              // 16 warps * 768 floats

    const int tid = threadIdx.x;
    const int wid = tid >> 5;
    const int lid = tid & 31;

    // pack: [kk][c][h] holds {W[4kk+2h][c], W[4kk+2h+1][c]}
    for (int i = tid; i < 4096; i += 512) {
        int kk = i >> 7, r = i & 127, c = r >> 1, h = r & 1;
        int k0 = 4*kk + 2*h;
        E1dq[i] = pk2(ew1[k0*64 + c],        ew1[(k0+1)*64 + c]);
        E1sq[i] = pk2(ew1[8192 + k0*64 + c], ew1[8192 + (k0+1)*64 + c]);
        D1q[i]  = pk2(dw1[k0*64 + c],        dw1[(k0+1)*64 + c]);
    }
    if (tid < 64) { be[tid] = eb1[tid]; bd[tid] = db1[tid]; }
    __syncthreads();

    float* xw = xs + wid * 768;

    for (int base = blockIdx.x*96 + wid*6; base < NN; base += gridDim.x*96) {
        #pragma unroll
        for (int m = 0; m < 6; m++) {
            int n = base + m;
            n = (n < NN) ? n : NN - 1;
            ((float4*)(xw + m*128))[lid] = ((const float4*)(x + (size_t)n*DD))[lid];
        }
        __syncwarp();

        u64 a[6][6];                      // [q][m]
        #pragma unroll
        for (int q = 0; q < 6; q++)
            #pragma unroll
            for (int m = 0; m < 6; m++) a[q][m] = 0ull;

        #pragma unroll 2
        for (int kk = 0; kk < 32; kk++) {             // covers k = 4kk .. 4kk+3
            const u64* p0 = E1dq + kk*128;
            const u64* p1 = E1sq + kk*128;
            const u64* p2 = D1q  + kk*128;
            ulonglong2 w0 = *(const ulonglong2*)(p0 + 2*lid);
            ulonglong2 w1 = *(const ulonglong2*)(p0 + 64 + 2*lid);
            ulonglong2 w2 = *(const ulonglong2*)(p1 + 2*lid);
            ulonglong2 w3 = *(const ulonglong2*)(p1 + 64 + 2*lid);
            ulonglong2 w4 = *(const ulonglong2*)(p2 + 2*lid);
            ulonglong2 w5 = *(const ulonglong2*)(p2 + 64 + 2*lid);
            #pragma unroll
            for (int m = 0; m < 6; m++) {
                float4 xv = *(const float4*)(xw + m*128 + kk*4);
                u64 blo = pk2(xv.x, xv.y);
                u64 bhi = pk2(xv.z, xv.w);
                fma2(a[0][m], blo, w0.x); fma2(a[0][m], bhi, w0.y);
                fma2(a[1][m], blo, w1.x); fma2(a[1][m], bhi, w1.y);
                fma2(a[2][m], blo, w2.x); fma2(a[2][m], bhi, w2.y);
                fma2(a[3][m], blo, w3.x); fma2(a[3][m], bhi, w3.y);
                fma2(a[4][m], blo, w4.x); fma2(a[4][m], bhi, w4.y);
                fma2(a[5][m], blo, w5.x); fma2(a[5][m], bhi, w5.y);
            }
        }

        #pragma unroll
        for (int m = 0; m < 6; m++) {
            int n = base + m;
            if (n >= NN) continue;
            size_t o = (size_t)n * 64;
            float lo, hi;
            upk2(a[0][m], lo, hi); g_hdst[o + lid]      = lo + hi + be[lid];
            upk2(a[1][m], lo, hi); g_hdst[o + 32 + lid] = lo + hi + be[32 + lid];
            upk2(a[2][m], lo, hi); g_hsrc[o + lid]      = lo + hi;
            upk2(a[3][m], lo, hi); g_hsrc[o + 32 + lid] = lo + hi;
            upk2(a[4][m], lo, hi); g_gdeg[o + lid]      = lo + hi + bd[lid];
            upk2(a[5][m], lo, hi); g_gdeg[o + 32 + lid] = lo + hi + bd[32 + lid];
        }
        __syncwarp();
    }
}

// ---------------------------------------------------------------------------
// Kernel B: edge energies. Warp = ONE NODE (all 15 edges): W2 read once per
// node instead of twice. Per k2: 2 weight LDS.128 (8 phases) + 15 broadcast
// LDS.128 (15 phases) + 60 FFMA2.
// ---------------------------------------------------------------------------
__global__ __launch_bounds__(256, 2)
void edge_kernel(const int* __restrict__ eidx,
                 const float* __restrict__ edist,
                 const float* __restrict__ ew1,
                 const float* __restrict__ ew2, const float* __restrict__ eb2,
                 const float* __restrict__ ew3, const float* __restrict__ eb3,
                 float* __restrict__ out_e)
{
    extern __shared__ float s[];
    u64* W2q = (u64*)s;                 // 2048 u64  [16 k2][64 c][2]
    float* w256 = (float*)(W2q + 2048); // 64 (ew1 row 256: dist weights)
    float* b2s  = w256 + 64;            // 64
    float* W3e  = b2s + 64;             // 64
    u64* tiles  = (u64*)(W3e + 64);     // 8 warps * 512 u64

    const int tid = threadIdx.x;
    const int wid = tid >> 5;
    const int lid = tid & 31;

    // pack: [k2][c][h] holds {W2[2k2+h][c], W2[2k2+h+32][c]}
    for (int i = tid; i < 2048; i += 256) {
        int k2 = i >> 7, r = i & 127, c = r >> 1, h = r & 1;
        int k = 2*k2 + h;
        W2q[i] = pk2(ew2[k*64 + c], ew2[(k+32)*64 + c]);
    }
    if (tid < 64) { w256[tid] = ew1[256*64 + tid]; b2s[tid] = eb2[tid]; W3e[tid] = ew3[tid]; }
    const float b3e = eb3[0];
    __syncthreads();

    u64* tile = tiles + wid * 512;

    for (int node = blockIdx.x*8 + wid; node < NN; node += gridDim.x*8) {
        const float hd0 = g_hdst[(size_t)node*64 + lid];
        const float hd1 = g_hdst[(size_t)node*64 + 32 + lid];
        const float wda = w256[lid], wdb = w256[32 + lid];

        #pragma unroll
        for (int m = 0; m < KK; m++) {
            int src  = __ldg(eidx + node*KK + m);
            float dm = __ldg(edist + node*KK + m);
            float hs0 = g_hsrc[(size_t)src*64 + lid];
            float hs1 = g_hsrc[(size_t)src*64 + 32 + lid];
            float h0 = fmaxf(fmaf(dm, wda, hd0 + hs0), 0.f);
            float h1 = fmaxf(fmaf(dm, wdb, hd1 + hs1), 0.f);
            tile[m*32 + lid] = pk2(h0, h1);     // {h[lid], h[lid+32]}
        }
        __syncwarp();

        u64 accA[KK], accB[KK];
        #pragma unroll
        for (int m = 0; m < KK; m++) { accA[m] = 0ull; accB[m] = 0ull; }

        #pragma unroll 2
        for (int k2 = 0; k2 < 16; k2++) {        // covers k = 2k2, 2k2+1 (+32)
            const u64* wr = W2q + k2*128;
            ulonglong2 wa = *(const ulonglong2*)(wr + 2*lid);
            ulonglong2 wb = *(const ulonglong2*)(wr + 64 + 2*lid);
            #pragma unroll
            for (int m = 0; m < KK; m++) {
                ulonglong2 f = *(const ulonglong2*)(tile + m*32 + 2*k2);
                fma2(accA[m], f.x, wa.x); fma2(accA[m], f.y, wa.y);
                fma2(accB[m], f.x, wb.x); fma2(accB[m], f.y, wb.y);
            }
        }

        const float w3a = W3e[lid], w3b = W3e[32 + lid];
        const float bb0 = b2s[lid], bb1 = b2s[32 + lid];
        float p[KK];
        #pragma unroll
        for (int m = 0; m < KK; m++) {
            float lo, hi;
            upk2(accA[m], lo, hi); float cA = lo + hi + bb0;
            upk2(accB[m], lo, hi); float cB = lo + hi + bb1;
            p[m] = fmaxf(cA, 0.f)*w3a + fmaxf(cB, 0.f)*w3b;
        }
        #pragma unroll
        for (int off = 16; off; off >>= 1) {
            #pragma unroll
            for (int m = 0; m < KK; m++)
                p[m] += __shfl_xor_sync(0xffffffffu, p[m], off);
        }

        float pm = p[0];
        #pragma unroll
        for (int m = 1; m < KK; m++) pm = (lid == m) ? p[m] : pm;
        if (lid < KK) {
            float E = 1.f / (1.f + expf(-2.f * (pm + b3e)));  // sigmoid(logit/0.5)
            out_e[node*KK + lid] = E;
        }
        __syncwarp();
    }
}

// ---------------------------------------------------------------------------
// Kernel C: degree MLP + rank gate, FOUR nodes per warp (D2 weight reads
// amortized 4x: 48 crossbar phases/node vs 144).
// ---------------------------------------------------------------------------
__global__ __launch_bounds__(256)
void node_kernel(const float* __restrict__ dw1,
                 const float* __restrict__ dw2, const float* __restrict__ db2,
                 const float* __restrict__ dw3, const float* __restrict__ db3,
                 const float* __restrict__ energy,
                 float* __restrict__ out_w, float* __restrict__ out_g,
                 float* __restrict__ out_k)
{
    extern __shared__ float s[];
    u64* D2q = (u64*)s;                 // 2048 u64  [16 k2][64 c][2]
    float* dwh = (float*)(D2q + 2048);  // 64 (dw1 row 128: hint weights)
    float* b2d = dwh + 64;              // 64
    float* W3d = b2d + 64;              // 64
    float* es  = W3d + 64;              // 8 warps * 64  (4 nodes x 16)
    u64* g1s   = (u64*)(es + 512);      // 8 warps * 128 u64 (4 nodes x 32)

    const int tid = threadIdx.x;
    const int wid = tid >> 5;
    const int lid = tid & 31;

    for (int i = tid; i < 2048; i += 256) {
        int k2 = i >> 7, r = i & 127, c = r >> 1, h = r & 1;
        int k = 2*k2 + h;
        D2q[i] = pk2(dw2[k*64 + c], dw2[(k+32)*64 + c]);
    }
    if (tid < 64) { dwh[tid] = dw1[128*64 + tid]; b2d[tid] = db2[tid]; W3d[tid] = dw3[tid]; }
    const float b3d = db3[0];
    __syncthreads();

    u64* g1    = g1s + wid * 128;
    float* esw = es + wid * 64;

    for (int base = blockIdx.x*32 + wid*4; base < NN; base += gridDim.x*32) {
        int n[4];
        float Ej[4];
        #pragma unroll
        for (int j = 0; j < 4; j++) {
            n[j] = (base + j < NN) ? base + j : NN - 1;
            float E = (lid < KK) ? energy[n[j]*KK + lid] : 0.f;
            Ej[j] = E;
            if (lid < 16) esw[j*16 + lid] = E;     // slot 15 = 0
            float hint = E;
            #pragma unroll
            for (int off = 16; off; off >>= 1) hint += __shfl_xor_sync(0xffffffffu, hint, off);
            // layer 1: lane computes cols (lid, lid+32), stores packed
            float a0 = fmaxf(fmaf(hint, dwh[lid],      g_gdeg[(size_t)n[j]*64 + lid]),      0.f);
            float a1 = fmaxf(fmaf(hint, dwh[32 + lid], g_gdeg[(size_t)n[j]*64 + 32 + lid]), 0.f);
            g1[j*32 + lid] = pk2(a0, a1);
        }
        __syncwarp();

        // layer 2 (64 -> 64) for 4 nodes, weights read once
        u64 accA[4], accB[4];
        #pragma unroll
        for (int j = 0; j < 4; j++) { accA[j] = 0ull; accB[j] = 0ull; }
        #pragma unroll 2
        for (int k2 = 0; k2 < 16; k2++) {
            const u64* wr = D2q + k2*128;
            ulonglong2 wa = *(const ulonglong2*)(wr + 2*lid);
            ulonglong2 wb = *(const ulonglong2*)(wr + 64 + 2*lid);
            #pragma unroll
            for (int j = 0; j < 4; j++) {
                ulonglong2 f = *(const ulonglong2*)(g1 + j*32 + 2*k2);
                fma2(accA[j], f.x, wa.x); fma2(accA[j], f.y, wa.y);
                fma2(accB[j], f.x, wb.x); fma2(accB[j], f.y, wb.y);
            }
        }

        #pragma unroll
        for (int j = 0; j < 4; j++) {
            float lo, hi;
            upk2(accA[j], lo, hi); float c0 = lo + hi + b2d[lid];
            upk2(accB[j], lo, hi); float c1 = lo + hi + b2d[32 + lid];
            float pkv = fmaxf(c0, 0.f)*W3d[lid] + fmaxf(c1, 0.f)*W3d[32 + lid];
            #pragma unroll
            for (int off = 16; off; off >>= 1) pkv += __shfl_xor_sync(0xffffffffu, pkv, off);
            const float kcont = 2.0f + 13.0f / (1.f + expf(-(pkv + b3d)));
            const bool valid = (base + j < NN);
            if (lid == 0 && valid) out_k[n[j]] = kcont;

            // hard top-k gate via rank (stable ties by index) + normalize
            float kint = rintf(kcont);
            kint = fminf(fmaxf(kint, 2.f), 15.f);
            float E = Ej[j];
            int cnt = 0;
            #pragma unroll
            for (int jj = 0; jj < KK; jj++) {
                float Ex = esw[j*16 + jj];
                cnt += (Ex > E) || (Ex == E && jj < lid);
            }
            const float gate = ((float)(cnt + 1) <= kint) ? 1.f : 0.f;
            const float wgt  = (lid < KK) ? E * gate : 0.f;
            float denom = wgt;
            #pragma unroll
            for (int off = 16; off; off >>= 1) denom += __shfl_xor_sync(0xffffffffu, denom, off);
            denom = fmaxf(denom, 1e-12f);
            if (lid < KK && valid) {
                out_g[n[j]*KK + lid] = gate;
                out_w[n[j]*KK + lid] = wgt / denom;
            }
        }
        __syncwarp();
    }
}

extern "C" void kernel_launch(void* const* d_in, const int* in_sizes, int n_in,
                              void* d_out, int out_size)
{
    const float* x     = (const float*)d_in[0];
    const int*   eidx  = (const int*)d_in[1];    // int32 (JAX x64 disabled); row 0 = src
    const float* edist = (const float*)d_in[2];
    const float* ew1   = (const float*)d_in[3];
    const float* eb1   = (const float*)d_in[4];
    const float* ew2   = (const float*)d_in[5];
    const float* eb2   = (const float*)d_in[6];
    const float* ew3   = (const float*)d_in[7];
    const float* eb3   = (const float*)d_in[8];
    const float* dw1   = (const float*)d_in[9];
    const float* db1   = (const float*)d_in[10];
    const float* dw2   = (const float*)d_in[11];
    const float* db2   = (const float*)d_in[12];
    const float* dw3   = (const float*)d_in[13];
    const float* db3   = (const float*)d_in[14];

    float* out   = (float*)d_out;
    float* out_w = out;               // edge_weight  (N*K)
    float* out_g = out + NKE;         // edge_gate    (N*K)
    float* out_e = out + 2*NKE;       // edge_energy  (N*K)
    float* out_k = out + 3*NKE;       // k_cont       (N)

    const int smemA = 3*4096*8 + 128*4 + 16*768*4;         // 147,968 B
    const int smemB = 2048*8 + 192*4 + 8*512*8;            //  49,920 B
    const int smemC = 2048*8 + 192*4 + 512*4 + 8*128*8;    //  27,392 B
    cudaFuncSetAttribute(precompute_kernel, cudaFuncAttributeMaxDynamicSharedMemorySize, smemA);
    cudaFuncSetAttribute(edge_kernel,       cudaFuncAttributeMaxDynamicSharedMemorySize, smemB);
    cudaFuncSetAttribute(node_kernel,       cudaFuncAttributeMaxDynamicSharedMemorySize, smemC);

    precompute_kernel<<<148, 512, smemA>>>(x, ew1, eb1, dw1, db1);
    edge_kernel<<<296, 256, smemB>>>(eidx, edist, ew1, ew2, eb2, ew3, eb3, out_e);
    node_kernel<<<296, 256, smemC>>>(dw1, dw2, db2, dw3, db3, out_e, out_w, out_g, out_k);
}

// round 17
// speedup vs baseline: 1.4464x; 1.2725x over previous
#include <cuda_runtime.h>
#include <cuda_bf16.h>

#define NN 50000
#define KK 15
#define DD 128
#define HH 64
#define NKE (NN*KK)
#define NT16 (NKE/16)        // 46875 tiles of 16 edges (exact)

typedef unsigned long long u64;
typedef unsigned int u32;

// Packed f32x2 helpers (scalar kernels).
__device__ __forceinline__ u64 pk2(float lo, float hi) {
    u64 r; asm("mov.b64 %0, {%1, %2};" : "=l"(r) : "f"(lo), "f"(hi)); return r;
}
__device__ __forceinline__ void upk2(u64 v, float& lo, float& hi) {
    asm("mov.b64 {%0, %1}, %2;" : "=f"(lo), "=f"(hi) : "l"(v));
}
__device__ __forceinline__ void fma2(u64& d, u64 a, u64 b) {
    asm("fma.rn.f32x2 %0, %1, %2, %0;" : "+l"(d) : "l"(a), "l"(b));
}

// HMMA helpers (baseline PTX, no 'a'-gated features).
__device__ __forceinline__ void ldsm4(u32* r, u32 addr) {
    asm volatile("ldmatrix.sync.aligned.m8n8.x4.shared.b16 {%0,%1,%2,%3}, [%4];\n"
        : "=r"(r[0]), "=r"(r[1]), "=r"(r[2]), "=r"(r[3]) : "r"(addr));
}
__device__ __forceinline__ void mma16816(float* d, const u32* a, u32 b0, u32 b1) {
    asm volatile("mma.sync.aligned.m16n8k16.row.col.f32.bf16.bf16.f32 "
        "{%0,%1,%2,%3}, {%4,%5,%6,%7}, {%8,%9}, {%0,%1,%2,%3};\n"
        : "+f"(d[0]), "+f"(d[1]), "+f"(d[2]), "+f"(d[3])
        : "r"(a[0]), "r"(a[1]), "r"(a[2]), "r"(a[3]), "r"(b0), "r"(b1));
}

// Precomputed per-node projections.
__device__ float g_hdst[NN*64];   // x @ ew1[0:128]   + eb1
__device__ float g_hsrc[NN*64];   // x @ ew1[128:256]
__device__ float g_gdeg[NN*64];   // x @ dw1[0:128]   + db1

// ---------------------------------------------------------------------------
// Kernel A (measured 69us): three fused 128x64 projections, FFMA2+LDS.128.
// ---------------------------------------------------------------------------
__global__ __launch_bounds__(512)
void precompute_kernel(const float* __restrict__ x,
                       const float* __restrict__ ew1, const float* __restrict__ eb1,
                       const float* __restrict__ dw1, const float* __restrict__ db1)
{
    extern __shared__ float s[];
    u64* E1dq = (u64*)s;
    u64* E1sq = E1dq + 4096;
    u64* D1q  = E1sq + 4096;
    float* be = (float*)(D1q + 4096);
    float* bd = be + 64;
    float* xs = bd + 64;

    const int tid = threadIdx.x;
    const int wid = tid >> 5;
    const int lid = tid & 31;

    for (int i = tid; i < 4096; i += 512) {
        int kk = i >> 7, r = i & 127, c = r >> 1, h = r & 1;
        int k0 = 4*kk + 2*h;
        E1dq[i] = pk2(ew1[k0*64 + c],        ew1[(k0+1)*64 + c]);
        E1sq[i] = pk2(ew1[8192 + k0*64 + c], ew1[8192 + (k0+1)*64 + c]);
        D1q[i]  = pk2(dw1[k0*64 + c],        dw1[(k0+1)*64 + c]);
    }
    if (tid < 64) { be[tid] = eb1[tid]; bd[tid] = db1[tid]; }
    __syncthreads();

    float* xw = xs + wid * 512;

    for (int base = blockIdx.x*64 + wid*4; base < NN; base += gridDim.x*64) {
        #pragma unroll
        for (int m = 0; m < 4; m++) {
            int n = (base + m < NN) ? base + m : NN - 1;
            ((float4*)(xw + m*128))[lid] = ((const float4*)(x + (size_t)n*DD))[lid];
        }
        __syncwarp();

        u64 a[6][4];
        #pragma unroll
        for (int q = 0; q < 6; q++)
            #pragma unroll
            for (int m = 0; m < 4; m++) a[q][m] = 0ull;

        #pragma unroll 2
        for (int kk = 0; kk < 32; kk++) {
            u64 bx[4][2];
            #pragma unroll
            for (int m = 0; m < 4; m++) {
                float4 xv = *(const float4*)(xw + m*128 + kk*4);
                bx[m][0] = pk2(xv.x, xv.y);
                bx[m][1] = pk2(xv.z, xv.w);
            }
            const u64* p0 = E1dq + kk*128;
            const u64* p1 = E1sq + kk*128;
            const u64* p2 = D1q  + kk*128;
            ulonglong2 w0 = *(const ulonglong2*)(p0 + 2*lid);
            ulonglong2 w1 = *(const ulonglong2*)(p0 + 64 + 2*lid);
            ulonglong2 w2 = *(const ulonglong2*)(p1 + 2*lid);
            ulonglong2 w3 = *(const ulonglong2*)(p1 + 64 + 2*lid);
            ulonglong2 w4 = *(const ulonglong2*)(p2 + 2*lid);
            ulonglong2 w5 = *(const ulonglong2*)(p2 + 64 + 2*lid);
            #pragma unroll
            for (int m = 0; m < 4; m++) {
                fma2(a[0][m], bx[m][0], w0.x); fma2(a[0][m], bx[m][1], w0.y);
                fma2(a[1][m], bx[m][0], w1.x); fma2(a[1][m], bx[m][1], w1.y);
                fma2(a[2][m], bx[m][0], w2.x); fma2(a[2][m], bx[m][1], w2.y);
                fma2(a[3][m], bx[m][0], w3.x); fma2(a[3][m], bx[m][1], w3.y);
                fma2(a[4][m], bx[m][0], w4.x); fma2(a[4][m], bx[m][1], w4.y);
                fma2(a[5][m], bx[m][0], w5.x); fma2(a[5][m], bx[m][1], w5.y);
            }
        }

        #pragma unroll
        for (int m = 0; m < 4; m++) {
            int n = base + m;
            if (n >= NN) continue;
            size_t o = (size_t)n * 64;
            float lo, hi;
            upk2(a[0][m], lo, hi); g_hdst[o + lid]      = lo + hi + be[lid];
            upk2(a[1][m], lo, hi); g_hdst[o + 32 + lid] = lo + hi + be[32 + lid];
            upk2(a[2][m], lo, hi); g_hsrc[o + lid]      = lo + hi;
            upk2(a[3][m], lo, hi); g_hsrc[o + 32 + lid] = lo + hi;
            upk2(a[4][m], lo, hi); g_gdeg[o + lid]      = lo + hi + bd[lid];
            upk2(a[5][m], lo, hi); g_gdeg[o + 32 + lid] = lo + hi + bd[32 + lid];
        }
        __syncwarp();
    }
}

// ---------------------------------------------------------------------------
// Kernel B: edge energies via mma.sync (HMMA) bf16 fp32-emulated GEMM.
// Warp-tile = 16 edges. h1 split 3-way (hi/mid/lo bf16); W2 likewise;
// D = sum of 6 split products, fp32 accumulators in registers.
// SMEM byte layout (per block):
//   [0)          BT splits: 3 x 64 rows x 144B     = 27648
//   [27648)      A staging: 8 warps x 3 x 16x144B  = 55296
//   [82944)      b2 (256), W3 (256), w256 (256)
//   [83712)      es: 8 warps x 16 floats           = 512
//   total 84224 -> 2 blocks/SM
// ---------------------------------------------------------------------------
#define EB_BT    0
#define EB_A     27648
#define EB_B2    82944
#define EB_W3    83200
#define EB_W256  83456
#define EB_ES    83712
#define EB_TOTAL 84224

__global__ __launch_bounds__(256)
void edge_tensor_kernel(const int* __restrict__ eidx,
                        const float* __restrict__ edist,
                        const float* __restrict__ ew1,
                        const float* __restrict__ ew2, const float* __restrict__ eb2,
                        const float* __restrict__ ew3, const float* __restrict__ eb3,
                        float* __restrict__ out_e)
{
    extern __shared__ char smem[];
    u32 sb;
    asm("{ .reg .u64 t; cvta.to.shared.u64 t, %1; cvt.u32.u64 %0, t; }"
        : "=r"(sb) : "l"(smem));

    const int tid = threadIdx.x;
    const int wid = tid >> 5;
    const int lid = tid & 31;

    float* b2s   = (float*)(smem + EB_B2);
    float* W3s   = (float*)(smem + EB_W3);
    float* w256s = (float*)(smem + EB_W256);
    float* es    = (float*)(smem + EB_ES) + wid*16;

    // ---- stage W2 splits as BT[n][k] (col-major B), 144B row stride ----
    for (int i = tid; i < 4096; i += 256) {
        int n = i >> 6, k = i & 63;
        float w = ew2[k*64 + n];
        __nv_bfloat16 bhi = __float2bfloat16_rn(w);
        float r = w - __bfloat162float(bhi);
        __nv_bfloat16 bmid = __float2bfloat16_rn(r);
        float r2 = r - __bfloat162float(bmid);
        __nv_bfloat16 blo = __float2bfloat16_rn(r2);
        u32 off = (u32)(n*144 + k*2);
        *(__nv_bfloat16*)(smem + EB_BT + off)         = bhi;
        *(__nv_bfloat16*)(smem + EB_BT + 9216 + off)  = bmid;
        *(__nv_bfloat16*)(smem + EB_BT + 18432 + off) = blo;
    }
    if (tid < 64) {
        b2s[tid]   = eb2[tid];
        W3s[tid]   = ew3[tid];
        w256s[tid] = ew1[256*64 + tid];
    }
    const float b3e = eb3[0];
    __syncthreads();

    // per-lane ldmatrix address templates
    const int j   = lid & 7;
    const int rs8 = (lid >> 3) & 1;        // +8 rows for fragments a1/a3
    const int ks8 = (lid >> 4) & 1;        // +8 k for fragments a2/a3
    const u32 a_pre = sb + EB_A + (u32)(wid*6912) + (u32)((j + rs8*8)*144 + ks8*16);
    const int g2  = lid >> 3;
    const u32 b_pre = sb + EB_BT + (u32)((j + (g2>>1)*8)*144 + (g2&1)*16);

    const float2 wdv = *(const float2*)(w256s + 2*lid);
    const int g = lid >> 2, t4 = lid & 3;

    for (int t16 = blockIdx.x*8 + wid; t16 < NT16; t16 += gridDim.x*8) {
        const int ebase = t16 * 16;

        // ---- stage A: layer-1 for 16 edges, 3-way bf16 split ----
        // lane owns k-columns (2lid, 2lid+1)
        {
            const u32 arow = sb + EB_A + (u32)(wid*6912) + (u32)(lid*4);
            #pragma unroll 4
            for (int e = 0; e < 16; e++) {
                const int eg   = ebase + e;
                const int node = eg / KK;
                const int src  = __ldg(eidx + eg);
                const float dm = __ldg(edist + eg);
                float2 hdv = *(const float2*)(g_hdst + (size_t)node*64 + 2*lid);
                float2 hsv = *(const float2*)(g_hsrc + (size_t)src*64  + 2*lid);
                float h0 = fmaxf(fmaf(dm, wdv.x, hdv.x + hsv.x), 0.f);
                float h1 = fmaxf(fmaf(dm, wdv.y, hdv.y + hsv.y), 0.f);

                __nv_bfloat16 h0h = __float2bfloat16_rn(h0);
                __nv_bfloat16 h1h = __float2bfloat16_rn(h1);
                float r0 = h0 - __bfloat162float(h0h);
                float r1 = h1 - __bfloat162float(h1h);
                __nv_bfloat16 h0m = __float2bfloat16_rn(r0);
                __nv_bfloat16 h1m = __float2bfloat16_rn(r1);
                float q0 = r0 - __bfloat162float(h0m);
                float q1 = r1 - __bfloat162float(h1m);
                __nv_bfloat16 h0l = __float2bfloat16_rn(q0);
                __nv_bfloat16 h1l = __float2bfloat16_rn(q1);

                u32 vhi = (u32)__bfloat16_as_ushort(h0h) | ((u32)__bfloat16_as_ushort(h1h) << 16);
                u32 vmi = (u32)__bfloat16_as_ushort(h0m) | ((u32)__bfloat16_as_ushort(h1m) << 16);
                u32 vlo = (u32)__bfloat16_as_ushort(h0l) | ((u32)__bfloat16_as_ushort(h1l) << 16);
                u32 ro = arow + (u32)(e*144);
                asm volatile("st.shared.b32 [%0], %1;" :: "r"(ro),         "r"(vhi) : "memory");
                asm volatile("st.shared.b32 [%0], %1;" :: "r"(ro + 2304u), "r"(vmi) : "memory");
                asm volatile("st.shared.b32 [%0], %1;" :: "r"(ro + 4608u), "r"(vlo) : "memory");
            }
        }
        __syncwarp();

        // ---- 6-product emulated GEMM: D[16x64] += split terms ----
        float d[8][4];
        #pragma unroll
        for (int nb = 0; nb < 8; nb++)
            #pragma unroll
            for (int c = 0; c < 4; c++) d[nb][c] = 0.f;

        #pragma unroll
        for (int kb = 0; kb < 4; kb++) {
            u32 afr[3][4];
            #pragma unroll
            for (int sa = 0; sa < 3; sa++)
                ldsm4(afr[sa], a_pre + (u32)(sa*2304 + kb*32));
            u32 bfr[3][4][4];                 // [split][q][frag]
            #pragma unroll
            for (int sbp = 0; sbp < 3; sbp++)
                #pragma unroll
                for (int q = 0; q < 4; q++)
                    ldsm4(bfr[sbp][q], b_pre + (u32)(sbp*9216 + q*2304 + kb*32));

            // products: (hi,hi) (hi,mid) (mid,hi) (hi,lo) (lo,hi) (mid,mid)
            const int SA[6] = {0, 0, 1, 0, 2, 1};
            const int SB[6] = {0, 1, 0, 2, 0, 1};
            #pragma unroll
            for (int p = 0; p < 6; p++) {
                #pragma unroll
                for (int q = 0; q < 4; q++) {
                    mma16816(d[2*q],   afr[SA[p]], bfr[SB[p]][q][0], bfr[SB[p]][q][1]);
                    mma16816(d[2*q+1], afr[SA[p]], bfr[SB[p]][q][2], bfr[SB[p]][q][3]);
                }
            }
        }

        // ---- epilogue: bias + relu + W3 dot + sigmoid ----
        float pr0 = 0.f, pr1 = 0.f;
        #pragma unroll
        for (int nb = 0; nb < 8; nb++) {
            float2 bb = *(const float2*)(b2s + nb*8 + 2*t4);
            float2 ww = *(const float2*)(W3s + nb*8 + 2*t4);
            pr0 += fmaxf(d[nb][0] + bb.x, 0.f)*ww.x + fmaxf(d[nb][1] + bb.y, 0.f)*ww.y;
            pr1 += fmaxf(d[nb][2] + bb.x, 0.f)*ww.x + fmaxf(d[nb][3] + bb.y, 0.f)*ww.y;
        }
        pr0 += __shfl_xor_sync(0xffffffffu, pr0, 1);
        pr0 += __shfl_xor_sync(0xffffffffu, pr0, 2);
        pr1 += __shfl_xor_sync(0xffffffffu, pr1, 1);
        pr1 += __shfl_xor_sync(0xffffffffu, pr1, 2);
        if (t4 == 0) { es[g] = pr0; es[8 + g] = pr1; }
        __syncwarp();
        if (lid < 16) {
            float E = 1.f / (1.f + expf(-2.f * (es[lid] + b3e)));  // sigmoid(logit/0.5)
            out_e[ebase + lid] = E;
        }
        __syncwarp();
    }
}

// ---------------------------------------------------------------------------
// Kernel C: degree MLP + rank gate, 4 nodes/warp (unchanged).
// ---------------------------------------------------------------------------
__global__ __launch_bounds__(256)
void node_kernel(const float* __restrict__ dw1,
                 const float* __restrict__ dw2, const float* __restrict__ db2,
                 const float* __restrict__ dw3, const float* __restrict__ db3,
                 const float* __restrict__ energy,
                 float* __restrict__ out_w, float* __restrict__ out_g,
                 float* __restrict__ out_k)
{
    extern __shared__ float s[];
    u64* D2q = (u64*)s;
    float* dwh = (float*)(D2q + 2048);
    float* b2d = dwh + 64;
    float* W3d = b2d + 64;
    float* es  = W3d + 64;
    u64* g1s   = (u64*)(es + 512);

    const int tid = threadIdx.x;
    const int wid = tid >> 5;
    const int lid = tid & 31;

    for (int i = tid; i < 2048; i += 256) {
        int k2 = i >> 7, r = i & 127, c = r >> 1, h = r & 1;
        int k = 2*k2 + h;
        D2q[i] = pk2(dw2[k*64 + c], dw2[(k+32)*64 + c]);
    }
    if (tid < 64) { dwh[tid] = dw1[128*64 + tid]; b2d[tid] = db2[tid]; W3d[tid] = dw3[tid]; }
    const float b3d = db3[0];
    __syncthreads();

    u64* g1    = g1s + wid * 128;
    float* esw = es + wid * 64;

    for (int base = blockIdx.x*32 + wid*4; base < NN; base += gridDim.x*32) {
        int n[4];
        float Ej[4];
        #pragma unroll
        for (int jx = 0; jx < 4; jx++) {
            n[jx] = (base + jx < NN) ? base + jx : NN - 1;
            float E = (lid < KK) ? energy[n[jx]*KK + lid] : 0.f;
            Ej[jx] = E;
            if (lid < 16) esw[jx*16 + lid] = E;
            float hint = E;
            #pragma unroll
            for (int off = 16; off; off >>= 1) hint += __shfl_xor_sync(0xffffffffu, hint, off);
            float a0 = fmaxf(fmaf(hint, dwh[lid],      g_gdeg[(size_t)n[jx]*64 + lid]),      0.f);
            float a1 = fmaxf(fmaf(hint, dwh[32 + lid], g_gdeg[(size_t)n[jx]*64 + 32 + lid]), 0.f);
            g1[jx*32 + lid] = pk2(a0, a1);
        }
        __syncwarp();

        u64 accA[4], accB[4];
        #pragma unroll
        for (int jx = 0; jx < 4; jx++) { accA[jx] = 0ull; accB[jx] = 0ull; }
        #pragma unroll 2
        for (int k2 = 0; k2 < 16; k2++) {
            const u64* wr = D2q + k2*128;
            ulonglong2 wa = *(const ulonglong2*)(wr + 2*lid);
            ulonglong2 wb = *(const ulonglong2*)(wr + 64 + 2*lid);
            #pragma unroll
            for (int jx = 0; jx < 4; jx++) {
                ulonglong2 f = *(const ulonglong2*)(g1 + jx*32 + 2*k2);
                fma2(accA[jx], f.x, wa.x); fma2(accA[jx], f.y, wa.y);
                fma2(accB[jx], f.x, wb.x); fma2(accB[jx], f.y, wb.y);
            }
        }

        #pragma unroll
        for (int jx = 0; jx < 4; jx++) {
            float lo, hi;
            upk2(accA[jx], lo, hi); float c0 = lo + hi + b2d[lid];
            upk2(accB[jx], lo, hi); float c1 = lo + hi + b2d[32 + lid];
            float pkv = fmaxf(c0, 0.f)*W3d[lid] + fmaxf(c1, 0.f)*W3d[32 + lid];
            #pragma unroll
            for (int off = 16; off; off >>= 1) pkv += __shfl_xor_sync(0xffffffffu, pkv, off);
            const float kcont = 2.0f + 13.0f / (1.f + expf(-(pkv + b3d)));
            const bool valid = (base + jx < NN);
            if (lid == 0 && valid) out_k[n[jx]] = kcont;

            float kint = rintf(kcont);
            kint = fminf(fmaxf(kint, 2.f), 15.f);
            float E = Ej[jx];
            int cnt = 0;
            #pragma unroll
            for (int jj = 0; jj < KK; jj++) {
                float Ex = esw[jx*16 + jj];
                cnt += (Ex > E) || (Ex == E && jj < lid);
            }
            const float gate = ((float)(cnt + 1) <= kint) ? 1.f : 0.f;
            const float wgt  = (lid < KK) ? E * gate : 0.f;
            float denom = wgt;
            #pragma unroll
            for (int off = 16; off; off >>= 1) denom += __shfl_xor_sync(0xffffffffu, denom, off);
            denom = fmaxf(denom, 1e-12f);
            if (lid < KK && valid) {
                out_g[n[jx]*KK + lid] = gate;
                out_w[n[jx]*KK + lid] = wgt / denom;
            }
        }
        __syncwarp();
    }
}

extern "C" void kernel_launch(void* const* d_in, const int* in_sizes, int n_in,
                              void* d_out, int out_size)
{
    const float* x     = (const float*)d_in[0];
    const int*   eidx  = (const int*)d_in[1];
    const float* edist = (const float*)d_in[2];
    const float* ew1   = (const float*)d_in[3];
    const float* eb1   = (const float*)d_in[4];
    const float* ew2   = (const float*)d_in[5];
    const float* eb2   = (const float*)d_in[6];
    const float* ew3   = (const float*)d_in[7];
    const float* eb3   = (const float*)d_in[8];
    const float* dw1   = (const float*)d_in[9];
    const float* db1   = (const float*)d_in[10];
    const float* dw2   = (const float*)d_in[11];
    const float* db2   = (const float*)d_in[12];
    const float* dw3   = (const float*)d_in[13];
    const float* db3   = (const float*)d_in[14];

    float* out   = (float*)d_out;
    float* out_w = out;
    float* out_g = out + NKE;
    float* out_e = out + 2*NKE;
    float* out_k = out + 3*NKE;

    const int smemA = 3*4096*8 + 128*4 + 16*512*4;         // 131,584 B
    const int smemB = EB_TOTAL;                            //  84,224 B
    const int smemC = 2048*8 + 192*4 + 512*4 + 8*128*8;    //  27,392 B
    cudaFuncSetAttribute(precompute_kernel,  cudaFuncAttributeMaxDynamicSharedMemorySize, smemA);
    cudaFuncSetAttribute(edge_tensor_kernel, cudaFuncAttributeMaxDynamicSharedMemorySize, smemB);
    cudaFuncSetAttribute(node_kernel,        cudaFuncAttributeMaxDynamicSharedMemorySize, smemC);

    precompute_kernel<<<148, 512, smemA>>>(x, ew1, eb1, dw1, db1);
    edge_tensor_kernel<<<296, 256, smemB>>>(eidx, edist, ew1, ew2, eb2, ew3, eb3, out_e);
    node_kernel<<<296, 256, smemC>>>(dw1, dw2, db2, dw3, db3, out_e, out_w, out_g, out_k);
}